// round 16
// baseline (speedup 1.0000x reference)
#include <cuda_runtime.h>
#include <cuda_fp16.h>
#include <cstdint>

// LSTM fused cell, legacy tensor path (family-target ISA — no tcgen05 on compute_103).
// Prepass: fp32 -> fp16 RN, concat [x|h_prev] -> g_Ah, [Wx|Rh] -> g_Wh.
// Main: mma.sync.m16n8k16.f16 (fp32 accum), ldmatrix.x4, CTA 256M x 32N x 4 gates,
//       256 threads, warp tile 64M x 16N x 4 gates (LDSM/MMA = 0.25),
//       BK=32, 4-stage cp.async pipeline, one barrier per K-tile, fused epilogue.

#define B_DIM 16384
#define H_DIM 1024
#define K_DIM 2048
#define NKT 64
#define BK 32
#define BM 256
#define BN 32           // per gate

#define PITCH 80        // bytes per smem row (64B data + 16B pad)
#define A_BYTES (BM * PITCH)            // 20480
#define B_BYTES (4 * BN * PITCH)        // 10240
#define BNP (BN * PITCH)                // 2560
#define STAGE (A_BYTES + B_BYTES)       // 30720
#define NSTAGE 4
#define SMEM_TOTAL (NSTAGE * STAGE)     // 122880 -> 1 CTA/SM

__device__ __half g_Ah[(size_t)B_DIM * K_DIM];       // 67 MB
__device__ __half g_Wh[(size_t)4 * H_DIM * K_DIM];   // 17 MB

__device__ __forceinline__ uint32_t smem_u32(const void* p) {
    uint32_t a;
    asm("{ .reg .u64 t; cvta.to.shared.u64 t, %1; cvt.u32.u64 %0, t; }" : "=r"(a) : "l"(p));
    return a;
}
__device__ __forceinline__ void cp16(uint32_t saddr, const void* gaddr) {
    asm volatile("cp.async.cg.shared.global [%0], [%1], 16;" :: "r"(saddr), "l"(gaddr));
}
__device__ __forceinline__ void cp_commit() {
    asm volatile("cp.async.commit_group;");
}
template <int N>
__device__ __forceinline__ void cp_wait() {
    asm volatile("cp.async.wait_group %0;" :: "n"(N));
}
__device__ __forceinline__ void ldsm_x4(uint32_t r[4], uint32_t addr) {
    asm volatile("ldmatrix.sync.aligned.m8n8.x4.shared.b16 {%0,%1,%2,%3}, [%4];"
                 : "=r"(r[0]), "=r"(r[1]), "=r"(r[2]), "=r"(r[3]) : "r"(addr));
}
__device__ __forceinline__ void mma_f16(float c[4], const uint32_t a[4], const uint32_t b[2]) {
    asm volatile(
        "mma.sync.aligned.m16n8k16.row.col.f32.f16.f16.f32 "
        "{%0,%1,%2,%3}, {%4,%5,%6,%7}, {%8,%9}, {%0,%1,%2,%3};"
        : "+f"(c[0]), "+f"(c[1]), "+f"(c[2]), "+f"(c[3])
        : "r"(a[0]), "r"(a[1]), "r"(a[2]), "r"(a[3]), "r"(b[0]), "r"(b[1]));
}
__device__ __forceinline__ float sigmoidf_fast(float x) {
    return 1.0f / (1.0f + __expf(-x));
}

// ================= prepass =================
#define NA8 (B_DIM * 256u)
#define NW8 (4u * H_DIM * 256u)

__global__ void __launch_bounds__(256)
prep_kernel(const float* __restrict__ x, const float* __restrict__ h_prev,
            const float* __restrict__ Wx, const float* __restrict__ Rh) {
    unsigned i = blockIdx.x * 256u + threadIdx.x;
    const float* src;
    __half* dst;
    if (i < NA8) {
        unsigned b = i >> 8, kc = i & 255;
        unsigned k0 = kc * 8;
        src = (k0 < 1024) ? x + (size_t)b * 1024 + k0
                          : h_prev + (size_t)b * 1024 + (k0 - 1024);
        dst = &g_Ah[(size_t)i * 8];
    } else {
        unsigned j = i - NA8;
        unsigned row = j >> 8, kc = j & 255;
        unsigned k0 = kc * 8;
        src = (k0 < 1024) ? Wx + (size_t)row * 1024 + k0
                          : Rh + (size_t)row * 1024 + (k0 - 1024);
        dst = &g_Wh[(size_t)j * 8];
    }
    float4 v0 = *reinterpret_cast<const float4*>(src);
    float4 v1 = *reinterpret_cast<const float4*>(src + 4);
    __half2 h0 = __floats2half2_rn(v0.x, v0.y);
    __half2 h1 = __floats2half2_rn(v0.z, v0.w);
    __half2 h2 = __floats2half2_rn(v1.x, v1.y);
    __half2 h3 = __floats2half2_rn(v1.z, v1.w);
    uint4 o = make_uint4(*(uint32_t*)&h0, *(uint32_t*)&h1, *(uint32_t*)&h2, *(uint32_t*)&h3);
    *reinterpret_cast<uint4*>(dst) = o;
}

// ================= main GEMM + fused epilogue =================
__global__ void __launch_bounds__(256, 1)
lstm_fp16_kernel(const float* __restrict__ c_prev,
                 const float* __restrict__ bx,
                 const float* __restrict__ bh,
                 float* __restrict__ out) {
    extern __shared__ __align__(16) uint8_t smem[];

    const int t = threadIdx.x;
    const int lid = t & 31;
    const int wp = t >> 5;        // 0..7
    const int gid = lid >> 2;     // 0..7
    const int tig = lid & 3;      // 0..3
    const int wm = wp >> 1;       // 0..3 -> 64-row slab
    const int wn = wp & 1;        // 0..1 -> 16-col slab (per gate)

    const int mBase = blockIdx.y * BM;
    const int hBase = blockIdx.x * BN;

    const uint32_t sb = smem_u32(smem);

    // ldmatrix base byte-offsets within a stage
    uint32_t aOff[4];
#pragma unroll
    for (int mi = 0; mi < 4; ++mi)
        aOff[mi] = (uint32_t)((wm * 64 + mi * 16 + (lid & 15)) * PITCH + (lid >> 4) * 16);
    const uint32_t bOff = (uint32_t)(A_BYTES +
        (wn * 16 + ((lid >> 4) << 3) + (lid & 7)) * PITCH + ((lid >> 3) & 1) * 16);

    // cp.async mapping.
    // A: 1024 16B-chunks (256 rows x 4): thread t handles rows t>>2 (+64p), chunk t&3.
    const int aRow0 = t >> 2, aC = t & 3;
    // B: 512 chunks (128 rows x 4): ids t and t+256.
    const int bRow0 = t >> 2;              // id0 = t    -> row t>>2,        chunk t&3
    const int bRow1 = (t + 256) >> 2;      // id1 = t+256 -> row 64 + (t>>2), chunk t&3

    const size_t gA0 = (size_t)(mBase + aRow0) * K_DIM + aC * 8;
    const size_t gA1 = (size_t)(mBase + aRow0 + 64) * K_DIM + aC * 8;
    const size_t gA2 = (size_t)(mBase + aRow0 + 128) * K_DIM + aC * 8;
    const size_t gA3 = (size_t)(mBase + aRow0 + 192) * K_DIM + aC * 8;
    const size_t gB0 = ((size_t)(bRow0 >> 5) * H_DIM + hBase + (bRow0 & 31)) * K_DIM + aC * 8;
    const size_t gB1 = ((size_t)(bRow1 >> 5) * H_DIM + hBase + (bRow1 & 31)) * K_DIM + aC * 8;
    const uint32_t sA0 = (uint32_t)(aRow0 * PITCH + aC * 16);
    const uint32_t sA1 = (uint32_t)((aRow0 + 64) * PITCH + aC * 16);
    const uint32_t sA2 = (uint32_t)((aRow0 + 128) * PITCH + aC * 16);
    const uint32_t sA3 = (uint32_t)((aRow0 + 192) * PITCH + aC * 16);
    const uint32_t sB0 = (uint32_t)(A_BYTES + bRow0 * PITCH + aC * 16);
    const uint32_t sB1 = (uint32_t)(A_BYTES + bRow1 * PITCH + aC * 16);

#define ISSUE_TILE(kt_, st_)                                   \
    do {                                                       \
        const uint32_t st = sb + (uint32_t)(st_) * STAGE;      \
        const int kOff = (kt_) * BK;                           \
        cp16(st + sA0, &g_Ah[gA0 + kOff]);                     \
        cp16(st + sA1, &g_Ah[gA1 + kOff]);                     \
        cp16(st + sA2, &g_Ah[gA2 + kOff]);                     \
        cp16(st + sA3, &g_Ah[gA3 + kOff]);                     \
        cp16(st + sB0, &g_Wh[gB0 + kOff]);                     \
        cp16(st + sB1, &g_Wh[gB1 + kOff]);                     \
        cp_commit();                                           \
    } while (0)

    // ---- prologue: issue K-tiles 0..2 ----
#pragma unroll
    for (int kt = 0; kt < NSTAGE - 1; ++kt) ISSUE_TILE(kt, kt);

    float acc[4][4][2][4];     // [gate][mi][ni][frag]
#pragma unroll
    for (int g = 0; g < 4; ++g)
#pragma unroll
        for (int mi = 0; mi < 4; ++mi)
#pragma unroll
            for (int ni = 0; ni < 2; ++ni)
#pragma unroll
                for (int k = 0; k < 4; ++k) acc[g][mi][ni][k] = 0.0f;

    // all 8 MMAs of one gate for one kk (4 mi x 2 ni)
#define MMA8(g, A, B)                                   \
    do {                                                \
        mma_f16(acc[g][0][0], (A)[0], (B) + 0);         \
        mma_f16(acc[g][0][1], (A)[0], (B) + 2);         \
        mma_f16(acc[g][1][0], (A)[1], (B) + 0);         \
        mma_f16(acc[g][1][1], (A)[1], (B) + 2);         \
        mma_f16(acc[g][2][0], (A)[2], (B) + 0);         \
        mma_f16(acc[g][2][1], (A)[2], (B) + 2);         \
        mma_f16(acc[g][3][0], (A)[3], (B) + 0);         \
        mma_f16(acc[g][3][1], (A)[3], (B) + 2);         \
    } while (0)

    int stage = 0;
    for (int kt = 0; kt < NKT; ++kt) {
        if (kt < NKT - 2)       cp_wait<2>();
        else if (kt == NKT - 2) cp_wait<1>();
        else                    cp_wait<0>();
        __syncthreads();

        // issue copies for tile kt+3 into the stage being freed
        if (kt + NSTAGE - 1 < NKT) {
            int s3 = stage + NSTAGE - 1;
            if (s3 >= NSTAGE) s3 -= NSTAGE;
            ISSUE_TILE(kt + NSTAGE - 1, s3);
        }

        // ---- compute on tile kt ----
        const uint32_t sst = sb + (uint32_t)stage * STAGE;
        {
            uint32_t a0[4][4], a1[4][4];
            uint32_t b0[4], b1[4], b2[4], b3[4];

            // kk = 0
            ldsm_x4(a0[0], sst + aOff[0]);
            ldsm_x4(a0[1], sst + aOff[1]);
            ldsm_x4(a0[2], sst + aOff[2]);
            ldsm_x4(a0[3], sst + aOff[3]);
            ldsm_x4(b0, sst + bOff + 0 * BNP);
            ldsm_x4(b1, sst + bOff + 1 * BNP);
            MMA8(0, a0, b0);
            ldsm_x4(b2, sst + bOff + 2 * BNP);
            MMA8(1, a0, b1);
            ldsm_x4(b3, sst + bOff + 3 * BNP);
            MMA8(2, a0, b2);
            ldsm_x4(a1[0], sst + aOff[0] + 32);
            ldsm_x4(a1[1], sst + aOff[1] + 32);
            ldsm_x4(a1[2], sst + aOff[2] + 32);
            ldsm_x4(a1[3], sst + aOff[3] + 32);
            MMA8(3, a0, b3);

            // kk = 1
            ldsm_x4(b0, sst + bOff + 0 * BNP + 32);
            ldsm_x4(b1, sst + bOff + 1 * BNP + 32);
            MMA8(0, a1, b0);
            ldsm_x4(b2, sst + bOff + 2 * BNP + 32);
            MMA8(1, a1, b1);
            ldsm_x4(b3, sst + bOff + 3 * BNP + 32);
            MMA8(2, a1, b2);
            MMA8(3, a1, b3);
        }

        stage = (stage + 1 == NSTAGE) ? 0 : stage + 1;
    }

    // ---- fused LSTM epilogue ----
#pragma unroll
    for (int mi = 0; mi < 4; ++mi) {
#pragma unroll
        for (int ni = 0; ni < 2; ++ni) {
#pragma unroll
            for (int rr = 0; rr < 2; ++rr) {
#pragma unroll
                for (int cc = 0; cc < 2; ++cc) {
                    const int r = mBase + wm * 64 + mi * 16 + gid + rr * 8;
                    const int col = hBase + wn * 16 + ni * 8 + tig * 2 + cc;
                    float pre[4];
#pragma unroll
                    for (int g = 0; g < 4; ++g) {
                        pre[g] = acc[g][mi][ni][rr * 2 + cc]
                               + __ldg(&bx[g * H_DIM + col])
                               + __ldg(&bh[g * H_DIM + col]);
                    }
                    const float z  = tanhf(pre[0]);
                    const float ig = sigmoidf_fast(pre[1]);
                    const float fg = sigmoidf_fast(pre[2]);
                    const float og = sigmoidf_fast(pre[3]);
                    const float cp = __ldg(&c_prev[(size_t)r * H_DIM + col]);
                    const float cn = fg * cp + ig * z;
                    const float hn = og * tanhf(cn);
                    out[(size_t)r * H_DIM + col] = hn;
                    out[(size_t)B_DIM * H_DIM + (size_t)r * H_DIM + col] = cn;
                }
            }
        }
    }
}

extern "C" void kernel_launch(void* const* d_in, const int* in_sizes, int n_in,
                              void* d_out, int out_size) {
    const float* x      = (const float*)d_in[0];
    const float* h_prev = (const float*)d_in[1];
    const float* c_prev = (const float*)d_in[2];
    const float* Wx     = (const float*)d_in[3];
    const float* bx     = (const float*)d_in[4];
    const float* Rh     = (const float*)d_in[5];
    const float* bh     = (const float*)d_in[6];
    float* out          = (float*)d_out;

    static int configured = 0;
    if (!configured) {
        cudaFuncSetAttribute(lstm_fp16_kernel,
                             cudaFuncAttributeMaxDynamicSharedMemorySize, SMEM_TOTAL);
        configured = 1;
    }

    prep_kernel<<<(NA8 + NW8) / 256, 256>>>(x, h_prev, Wx, Rh);

    dim3 grid(H_DIM / BN, B_DIM / BM, 1);   // (32, 64)
    lstm_fp16_kernel<<<grid, 256, SMEM_TOTAL>>>(c_prev, bx, bh, out);
}

// round 17
// speedup vs baseline: 1.4139x; 1.4139x over previous
#include <cuda_runtime.h>
#include <cuda_fp16.h>
#include <cstdint>

// LSTM fused cell, legacy tensor path (family-target ISA — no tcgen05 on compute_103).
// Prepass: fp32 -> fp16 RN, concat [x|h_prev] -> g_Ah, [Wx|Rh] -> g_Wh.
// Main: mma.sync.m16n8k16.f16 (fp32 accum), ldmatrix.x4, CTA 128M x 32N x 4 gates,
//       BK=32, 4-stage cp.async pipeline with PER-STAGE MBARRIERS (no __syncthreads
//       in the mainloop -> warps decouple), 2 CTAs/SM, fused LSTM epilogue.

#define B_DIM 16384
#define H_DIM 1024
#define K_DIM 2048
#define NKT 64
#define BK 32
#define BM 128
#define BN 32           // per gate

#define PITCH 80        // bytes per smem row (64B data + 16B pad)
#define A_BYTES (BM * PITCH)            // 10240
#define B_BYTES (4 * BN * PITCH)        // 10240
#define BNP (BN * PITCH)                // 2560
#define STAGE (A_BYTES + B_BYTES)       // 20480
#define NSTAGE 4
#define MBAR_BYTES 64
#define SMEM_TOTAL (NSTAGE * STAGE + MBAR_BYTES)   // 81984 -> 2 CTAs/SM

__device__ __half g_Ah[(size_t)B_DIM * K_DIM];       // 67 MB
__device__ __half g_Wh[(size_t)4 * H_DIM * K_DIM];   // 17 MB

__device__ __forceinline__ uint32_t smem_u32(const void* p) {
    uint32_t a;
    asm("{ .reg .u64 t; cvta.to.shared.u64 t, %1; cvt.u32.u64 %0, t; }" : "=r"(a) : "l"(p));
    return a;
}
__device__ __forceinline__ void cp16(uint32_t saddr, const void* gaddr) {
    asm volatile("cp.async.cg.shared.global [%0], [%1], 16;" :: "r"(saddr), "l"(gaddr));
}
__device__ __forceinline__ void cp_arrive_noinc(uint32_t mbar) {
    asm volatile("cp.async.mbarrier.arrive.noinc.shared.b64 [%0];" :: "r"(mbar) : "memory");
}
__device__ __forceinline__ void mbar_init(uint32_t mbar, uint32_t cnt) {
    asm volatile("mbarrier.init.shared.b64 [%0], %1;" :: "r"(mbar), "r"(cnt) : "memory");
}
__device__ __forceinline__ void mbar_arrive(uint32_t mbar) {
    asm volatile("mbarrier.arrive.shared.b64 _, [%0];" :: "r"(mbar) : "memory");
}
__device__ __forceinline__ void mbar_wait(uint32_t mbar, uint32_t parity) {
    asm volatile(
        "{\n\t.reg .pred P;\n\t"
        "WL_%=:\n\t"
        "mbarrier.try_wait.parity.shared.b64 P, [%0], %1, 0x989680;\n\t"
        "@P bra.uni WD_%=;\n\t"
        "bra.uni WL_%=;\n\t"
        "WD_%=:\n\t}"
        :: "r"(mbar), "r"(parity) : "memory");
}
__device__ __forceinline__ void ldsm_x4(uint32_t r[4], uint32_t addr) {
    asm volatile("ldmatrix.sync.aligned.m8n8.x4.shared.b16 {%0,%1,%2,%3}, [%4];"
                 : "=r"(r[0]), "=r"(r[1]), "=r"(r[2]), "=r"(r[3]) : "r"(addr));
}
__device__ __forceinline__ void mma_f16(float c[4], const uint32_t a[4], const uint32_t b[2]) {
    asm volatile(
        "mma.sync.aligned.m16n8k16.row.col.f32.f16.f16.f32 "
        "{%0,%1,%2,%3}, {%4,%5,%6,%7}, {%8,%9}, {%0,%1,%2,%3};"
        : "+f"(c[0]), "+f"(c[1]), "+f"(c[2]), "+f"(c[3])
        : "r"(a[0]), "r"(a[1]), "r"(a[2]), "r"(a[3]), "r"(b[0]), "r"(b[1]));
}
__device__ __forceinline__ float sigmoidf_fast(float x) {
    return 1.0f / (1.0f + __expf(-x));
}

// ================= prepass =================
#define NA8 (B_DIM * 256u)
#define NW8 (4u * H_DIM * 256u)

__global__ void __launch_bounds__(256)
prep_kernel(const float* __restrict__ x, const float* __restrict__ h_prev,
            const float* __restrict__ Wx, const float* __restrict__ Rh) {
    unsigned i = blockIdx.x * 256u + threadIdx.x;
    const float* src;
    __half* dst;
    if (i < NA8) {
        unsigned b = i >> 8, kc = i & 255;
        unsigned k0 = kc * 8;
        src = (k0 < 1024) ? x + (size_t)b * 1024 + k0
                          : h_prev + (size_t)b * 1024 + (k0 - 1024);
        dst = &g_Ah[(size_t)i * 8];
    } else {
        unsigned j = i - NA8;
        unsigned row = j >> 8, kc = j & 255;
        unsigned k0 = kc * 8;
        src = (k0 < 1024) ? Wx + (size_t)row * 1024 + k0
                          : Rh + (size_t)row * 1024 + (k0 - 1024);
        dst = &g_Wh[(size_t)j * 8];
    }
    float4 v0 = *reinterpret_cast<const float4*>(src);
    float4 v1 = *reinterpret_cast<const float4*>(src + 4);
    __half2 h0 = __floats2half2_rn(v0.x, v0.y);
    __half2 h1 = __floats2half2_rn(v0.z, v0.w);
    __half2 h2 = __floats2half2_rn(v1.x, v1.y);
    __half2 h3 = __floats2half2_rn(v1.z, v1.w);
    uint4 o = make_uint4(*(uint32_t*)&h0, *(uint32_t*)&h1, *(uint32_t*)&h2, *(uint32_t*)&h3);
    *reinterpret_cast<uint4*>(dst) = o;
}

// ================= main GEMM + fused epilogue =================
__global__ void __launch_bounds__(256, 2)
lstm_fp16_kernel(const float* __restrict__ c_prev,
                 const float* __restrict__ bx,
                 const float* __restrict__ bh,
                 float* __restrict__ out) {
    extern __shared__ __align__(16) uint8_t smem[];

    const int t = threadIdx.x;
    const int lid = t & 31;
    const int wp = t >> 5;
    const int gid = lid >> 2;     // 0..7
    const int tig = lid & 3;      // 0..3
    const int wm = wp >> 1;       // 0..3 -> 32-row slab
    const int wn = wp & 1;        // 0..1 -> 16-col slab (per gate)

    const int mBase = blockIdx.y * BM;
    const int hBase = blockIdx.x * BN;

    const uint32_t sb = smem_u32(smem);
    const uint32_t mb = sb + (uint32_t)(NSTAGE * STAGE);
#define MBAR_FULL(s)  (mb + (uint32_t)(s) * 8)
#define MBAR_EMPTY(s) (mb + 32 + (uint32_t)(s) * 8)

    // one-time mbarrier init (256 arrivals each: one per thread)
    if (t == 0) {
#pragma unroll
        for (int s = 0; s < NSTAGE; ++s) {
            mbar_init(MBAR_FULL(s), 256);
            mbar_init(MBAR_EMPTY(s), 256);
        }
    }
    __syncthreads();    // only CTA-wide barrier in the kernel

    // ldmatrix base byte-offsets within a stage
    uint32_t aOff[2];
#pragma unroll
    for (int mi = 0; mi < 2; ++mi)
        aOff[mi] = (uint32_t)((wm * 32 + mi * 16 + (lid & 15)) * PITCH + (lid >> 4) * 16);
    const uint32_t bOff = (uint32_t)(A_BYTES +
        (wn * 16 + ((lid >> 4) << 3) + (lid & 7)) * PITCH + ((lid >> 3) & 1) * 16);

    // cp.async mapping: 512 16B-chunks for A (128 rows x 4) and for B.
    const int cRow = t >> 2;          // 0..63  (+64 for second pass)
    const int cC = t & 3;             // 16B chunk in row

    const size_t gA0 = (size_t)(mBase + cRow) * K_DIM + cC * 8;
    const size_t gA1 = (size_t)(mBase + cRow + 64) * K_DIM + cC * 8;
    const int bRowA = cRow;           // gate = row>>5, n = row&31
    const int bRowB = cRow + 64;
    const size_t gB0 = ((size_t)(bRowA >> 5) * H_DIM + hBase + (bRowA & 31)) * K_DIM + cC * 8;
    const size_t gB1 = ((size_t)(bRowB >> 5) * H_DIM + hBase + (bRowB & 31)) * K_DIM + cC * 8;
    const uint32_t sA0 = (uint32_t)(cRow * PITCH + cC * 16);
    const uint32_t sA1 = (uint32_t)((cRow + 64) * PITCH + cC * 16);
    const uint32_t sB0 = (uint32_t)(A_BYTES + bRowA * PITCH + cC * 16);
    const uint32_t sB1 = (uint32_t)(A_BYTES + bRowB * PITCH + cC * 16);

#define ISSUE_TILE(kt_, st_)                                   \
    do {                                                       \
        const uint32_t st = sb + (uint32_t)(st_) * STAGE;      \
        const int kOff = (kt_) * BK;                           \
        cp16(st + sA0, &g_Ah[gA0 + kOff]);                     \
        cp16(st + sA1, &g_Ah[gA1 + kOff]);                     \
        cp16(st + sB0, &g_Wh[gB0 + kOff]);                     \
        cp16(st + sB1, &g_Wh[gB1 + kOff]);                     \
    } while (0)

    // ---- prologue: issue K-tiles 0..2, arriving on their full-barriers ----
#pragma unroll
    for (int kt = 0; kt < NSTAGE - 1; ++kt) {
        ISSUE_TILE(kt, kt);
        cp_arrive_noinc(MBAR_FULL(kt));
    }

    float acc[4][2][2][4];
#pragma unroll
    for (int g = 0; g < 4; ++g)
#pragma unroll
        for (int mi = 0; mi < 2; ++mi)
#pragma unroll
            for (int ni = 0; ni < 2; ++ni)
#pragma unroll
                for (int k = 0; k < 4; ++k) acc[g][mi][ni][k] = 0.0f;

#define MMA4(g, A, B)                                   \
    do {                                                \
        mma_f16(acc[g][0][0], (A)[0], (B) + 0);         \
        mma_f16(acc[g][0][1], (A)[0], (B) + 2);         \
        mma_f16(acc[g][1][0], (A)[1], (B) + 0);         \
        mma_f16(acc[g][1][1], (A)[1], (B) + 2);         \
    } while (0)

    for (int kt = 0; kt < NKT; ++kt) {
        // ---- producer: tile kt+3 into stage freed by tile kt-1 ----
        const int kn = kt + NSTAGE - 1;
        if (kn < NKT) {
            const int sn = kn & 3;
            if (kn >= NSTAGE)
                mbar_wait(MBAR_EMPTY(sn), ((kn >> 2) + 1) & 1);  // tile kn-4 consumed
            ISSUE_TILE(kn, sn);
            cp_arrive_noinc(MBAR_FULL(sn));
        }

        // ---- consumer: tile kt ----
        const int s = kt & 3;
        mbar_wait(MBAR_FULL(s), (kt >> 2) & 1);

        const uint32_t sst = sb + (uint32_t)s * STAGE;
        {
            uint32_t a0[2][4], a1[2][4];
            uint32_t b0[4], b1[4], b2[4], b3[4];

            // kk = 0
            ldsm_x4(a0[0], sst + aOff[0]);
            ldsm_x4(a0[1], sst + aOff[1]);
            ldsm_x4(b0, sst + bOff + 0 * BNP);
            ldsm_x4(b1, sst + bOff + 1 * BNP);
            MMA4(0, a0, b0);
            ldsm_x4(b2, sst + bOff + 2 * BNP);
            MMA4(1, a0, b1);
            ldsm_x4(b3, sst + bOff + 3 * BNP);
            MMA4(2, a0, b2);
            ldsm_x4(a1[0], sst + aOff[0] + 32);
            ldsm_x4(a1[1], sst + aOff[1] + 32);
            MMA4(3, a0, b3);

            // kk = 1
            ldsm_x4(b0, sst + bOff + 0 * BNP + 32);
            ldsm_x4(b1, sst + bOff + 1 * BNP + 32);
            MMA4(0, a1, b0);
            ldsm_x4(b2, sst + bOff + 2 * BNP + 32);
            MMA4(1, a1, b1);
            ldsm_x4(b3, sst + bOff + 3 * BNP + 32);
            MMA4(2, a1, b2);
            MMA4(3, a1, b3);
        }

        mbar_arrive(MBAR_EMPTY(s));
    }

    // ---- fused LSTM epilogue ----
#pragma unroll
    for (int mi = 0; mi < 2; ++mi) {
#pragma unroll
        for (int ni = 0; ni < 2; ++ni) {
#pragma unroll
            for (int rr = 0; rr < 2; ++rr) {
#pragma unroll
                for (int cc = 0; cc < 2; ++cc) {
                    const int r = mBase + wm * 32 + mi * 16 + gid + rr * 8;
                    const int col = hBase + wn * 16 + ni * 8 + tig * 2 + cc;
                    float pre[4];
#pragma unroll
                    for (int g = 0; g < 4; ++g) {
                        pre[g] = acc[g][mi][ni][rr * 2 + cc]
                               + __ldg(&bx[g * H_DIM + col])
                               + __ldg(&bh[g * H_DIM + col]);
                    }
                    const float z  = tanhf(pre[0]);
                    const float ig = sigmoidf_fast(pre[1]);
                    const float fg = sigmoidf_fast(pre[2]);
                    const float og = sigmoidf_fast(pre[3]);
                    const float cp = __ldg(&c_prev[(size_t)r * H_DIM + col]);
                    const float cn = fg * cp + ig * z;
                    const float hn = og * tanhf(cn);
                    out[(size_t)r * H_DIM + col] = hn;
                    out[(size_t)B_DIM * H_DIM + (size_t)r * H_DIM + col] = cn;
                }
            }
        }
    }
}

extern "C" void kernel_launch(void* const* d_in, const int* in_sizes, int n_in,
                              void* d_out, int out_size) {
    const float* x      = (const float*)d_in[0];
    const float* h_prev = (const float*)d_in[1];
    const float* c_prev = (const float*)d_in[2];
    const float* Wx     = (const float*)d_in[3];
    const float* bx     = (const float*)d_in[4];
    const float* Rh     = (const float*)d_in[5];
    const float* bh     = (const float*)d_in[6];
    float* out          = (float*)d_out;

    static int configured = 0;
    if (!configured) {
        cudaFuncSetAttribute(lstm_fp16_kernel,
                             cudaFuncAttributeMaxDynamicSharedMemorySize, SMEM_TOTAL);
        configured = 1;
    }

    prep_kernel<<<(NA8 + NW8) / 256, 256>>>(x, h_prev, Wx, Rh);

    dim3 grid(H_DIM / BN, B_DIM / BM, 1);   // (32, 128)
    lstm_fp16_kernel<<<grid, 256, SMEM_TOTAL>>>(c_prev, bx, bh, out);
}